// round 17
// baseline (speedup 1.0000x reference)
#include <cuda_runtime.h>
#include <cuda_fp16.h>
#include <math.h>
#include <stdint.h>

#define B_   16384
#define D_   256
#define ML_  10
#define M2_  (B_*9)

typedef __half h16;

// ---------------- fp16 scratch ----------------
__device__ __align__(256) h16 g_QK   [(size_t)B_*256];
__device__ __align__(256) h16 g_gates[(size_t)B_*768];
__device__ __align__(256) h16 g_OZH  [(size_t)B_*768];
__device__ __align__(256) h16 g_X   [(size_t)B_*512];
__device__ __align__(256) h16 g_OTP [(size_t)B_*256];
__device__ __align__(256) h16 g_WM  [(size_t)B_*256];
__device__ __align__(256) h16 g_OUP [(size_t)B_*256];
__device__ __align__(256) h16 g_ZRraw[(size_t)M2_*512];
// ---------------- fp16 weights ----------------
__device__ __align__(256) h16 g_Wigo [768*512];
__device__ __align__(256) h16 g_Wqk  [65536];
__device__ __align__(256) h16 g_Wv   [65536];
__device__ __align__(256) h16 g_Wzrm [512*256];
__device__ __align__(256) h16 g_Whm  [256*256];
__device__ __align__(256) h16 g_Wozh [768*256];
__device__ __align__(256) float g_bigo[768];
__device__ __align__(256) float g_bozh[768];
__device__ __align__(256) float g_bqk [256];

__device__ __forceinline__ float sigf(float x){ return 1.f/(1.f+expf(-x)); }

// ---------------- PTX helpers (base ISA only) ----------------
__device__ __forceinline__ uint32_t smem_u32(const void* p){
    uint32_t a; asm("{ .reg .u64 t; cvta.to.shared.u64 t, %1; cvt.u32.u64 %0, t; }" : "=r"(a) : "l"(p));
    return a;
}
__device__ __forceinline__ void ldsm4(uint32_t* r, uint32_t addr){
    asm volatile("ldmatrix.sync.aligned.m8n8.x4.shared.b16 {%0,%1,%2,%3}, [%4];"
        : "=r"(r[0]),"=r"(r[1]),"=r"(r[2]),"=r"(r[3]) : "r"(addr));
}
__device__ __forceinline__ void mma_f16(float* c, const uint32_t* a, const uint32_t* b){
    asm volatile("mma.sync.aligned.m16n8k16.row.col.f32.f16.f16.f32 "
        "{%0,%1,%2,%3}, {%4,%5,%6,%7}, {%8,%9}, {%0,%1,%2,%3};"
        : "+f"(c[0]),"+f"(c[1]),"+f"(c[2]),"+f"(c[3])
        : "r"(a[0]),"r"(a[1]),"r"(a[2]),"r"(a[3]), "r"(b[0]),"r"(b[1]));
}
__device__ __forceinline__ void cpa16(uint32_t dst, const void* src){
    asm volatile("cp.async.cg.shared.global [%0], [%1], 16;" :: "r"(dst), "l"(src));
}
#define CP_COMMIT() asm volatile("cp.async.commit_group;" ::: "memory")
#define CP_WAIT1()  asm volatile("cp.async.wait_group 1;"  ::: "memory")
#define CP_WAIT0()  asm volatile("cp.async.wait_group 0;"  ::: "memory")

#define ROWB     144
#define STAGE_SZ 36864
#define SMEM_TOTAL (3*STAGE_SZ)

// ================== fp16 HMMA GEMM: C[M,N] = A[M,K] @ W[N,K]^T ==================
// EPI 5: C16 fp16 = v + bias[col]
// EPI 2: V-mode: v+=bias; fp16(v) -> C16(=OUP); v -> out0, out2, out_mem slot 9
template<int EPI>
__global__ void __launch_bounds__(256,2) k_mma(
    const h16* __restrict__ A,
    const h16* __restrict__ W,
    const float* __restrict__ bias,
    h16* __restrict__ C16,
    float* __restrict__ out0, float* __restrict__ out_mem, float* __restrict__ out2,
    int M, int N, int K)
{
    extern __shared__ char smem[];
    uint32_t sb = smem_u32(smem);
    const int tid = threadIdx.x, lane = tid & 31, w = tid >> 5;
    const int wm = w >> 2, wn = w & 3;
    const int m0 = blockIdx.y * 128, n0 = blockIdx.x * 128;
    const int nch = K >> 6;

    float acc[4][4][4];
    #pragma unroll
    for (int i=0;i<4;i++)
        #pragma unroll
        for (int j=0;j<4;j++)
            #pragma unroll
            for (int k=0;k<4;k++) acc[i][j][k]=0.f;

    auto load_chunk = [&](int c, int s){
        uint32_t st = sb + s*STAGE_SZ;
        #pragma unroll
        for (int t=0;t<4;t++){
            int u = tid + t*256;
            int row = u >> 3, q = u & 7;
            cpa16(st + row*ROWB + q*16, A + (size_t)(m0+row)*K + c*64 + q*8);
        }
        #pragma unroll
        for (int t=0;t<4;t++){
            int u = tid + t*256;
            int row = u >> 3, q = u & 7;
            cpa16(st + 18432 + row*ROWB + q*16, W + (size_t)(n0+row)*K + c*64 + q*8);
        }
        CP_COMMIT();
    };

    load_chunk(0, 0);
    load_chunk(1, 1);

    for (int c = 0; c < nch; c++){
        if (c == nch - 1) CP_WAIT0(); else CP_WAIT1();
        __syncthreads();
        if (c + 2 < nch) load_chunk(c + 2, (c + 2) % 3);

        uint32_t sA = sb + (c % 3)*STAGE_SZ;
        uint32_t sW = sA + 18432;
        #pragma unroll
        for (int kk = 0; kk < 4; kk++){
            uint32_t a[4][4];
            #pragma unroll
            for (int i = 0; i < 4; i++){
                int rl = wm*64 + i*16 + (lane & 7) + ((lane & 8) ? 8 : 0);
                uint32_t colb = kk*32 + ((lane & 16) ? 16 : 0);
                ldsm4(a[i], sA + rl*ROWB + colb);
            }
            uint32_t bf[4][2];
            #pragma unroll
            for (int jp = 0; jp < 2; jp++){
                int nl = wn*32 + jp*16 + (lane & 7) + ((lane & 16) ? 8 : 0);
                uint32_t colb = kk*32 + ((lane & 8) ? 16 : 0);
                uint32_t t4[4];
                ldsm4(t4, sW + nl*ROWB + colb);
                bf[2*jp][0]=t4[0]; bf[2*jp][1]=t4[1]; bf[2*jp+1][0]=t4[2]; bf[2*jp+1][1]=t4[3];
            }
            #pragma unroll
            for (int i=0;i<4;i++)
                #pragma unroll
                for (int j=0;j<4;j++) mma_f16(acc[i][j], a[i], bf[j]);
        }
        __syncthreads();
    }

    #pragma unroll
    for (int j = 0; j < 4; j++){
        int col = n0 + wn*32 + j*8 + (lane & 3)*2;
        float b0 = bias ? bias[col]   : 0.f;
        float b1 = bias ? bias[col+1] : 0.f;
        #pragma unroll
        for (int i = 0; i < 4; i++){
            int row = m0 + wm*64 + i*16 + (lane >> 2);
            #pragma unroll
            for (int h = 0; h < 2; h++){
                int rr = row + h*8;
                float v0 = acc[i][j][2*h+0] + b0;
                float v1 = acc[i][j][2*h+1] + b1;
                if (EPI == 5){
                    *reinterpret_cast<__half2*>(C16 + (size_t)rr*N + col) = __floats2half2_rn(v0, v1);
                } else {  // EPI 2
                    size_t o = (size_t)rr*256 + col;
                    float2 fv = make_float2(v0, v1);
                    *reinterpret_cast<__half2*>(C16 + o) = __floats2half2_rn(v0, v1);
                    *reinterpret_cast<float2*>(out0 + o) = fv;
                    *reinterpret_cast<float2*>(out2 + o) = fv;
                    *reinterpret_cast<float2*>(out_mem + (size_t)rr*(ML_*256) + 9*256 + col) = fv;
                }
            }
        }
    }
}

// ================== k_zr: raw z|r GEMM [M2,512] from fp32 memory (overlap stream) ==================
#define ZR_ROWSTR 528
#define ZR_A_OFF  0
#define ZR_W_OFF  33792
#define ZR_WSTG   10240
#define ZR_SMEM   54272

__global__ void __launch_bounds__(256,2) k_zr(
    const float* __restrict__ memory,
    const h16* __restrict__ Wzrm,
    h16* __restrict__ zrraw)
{
    extern __shared__ char smem[];
    uint32_t sb = smem_u32(smem);
    const int tid = threadIdx.x, lane = tid & 31, w = tid >> 5;
    const int wm = w >> 2, wn = w & 3;
    const int m0 = blockIdx.x * 64;

    auto wload = [&](const h16* Wg, int c, int s){
        #pragma unroll
        for (int t = 0; t < 2; t++){
            int u = tid + t*256;
            int row = u >> 2, q = u & 3;
            cpa16(sb + ZR_W_OFF + s*ZR_WSTG + row*80 + q*16,
                  Wg + (size_t)row*256 + c*32 + q*8);
        }
        CP_COMMIT();
    };
    wload(Wzrm, 0, 0);
    wload(Wzrm, 1, 1);

    // A: 64 rows fp32 -> fp16 SMEM
    #pragma unroll
    for (int t = 0; t < 8; t++){
        int u = tid + t*256;
        int row = u >> 5, q = u & 31;
        int rr = m0 + row, b = rr/9, m = rr - b*9 + 1;
        const float* src = memory + ((size_t)b*10 + m)*256 + q*8;
        float4 a = *reinterpret_cast<const float4*>(src);
        float4 c = *reinterpret_cast<const float4*>(src + 4);
        __half2 o0 = __floats2half2_rn(a.x, a.y);
        __half2 o1 = __floats2half2_rn(a.z, a.w);
        __half2 o2 = __floats2half2_rn(c.x, c.y);
        __half2 o3 = __floats2half2_rn(c.z, c.w);
        uint4 pk;
        pk.x = *reinterpret_cast<uint32_t*>(&o0);
        pk.y = *reinterpret_cast<uint32_t*>(&o1);
        pk.z = *reinterpret_cast<uint32_t*>(&o2);
        pk.w = *reinterpret_cast<uint32_t*>(&o3);
        *reinterpret_cast<uint4*>(smem + ZR_A_OFF + row*ZR_ROWSTR + q*16) = pk;
    }
    __syncthreads();

    for (int pass = 0; pass < 4; pass++){
        const h16* Wg = Wzrm + (size_t)pass*(128*256);
        float acc[2][4][4];
        #pragma unroll
        for (int i=0;i<2;i++)
            #pragma unroll
            for (int j=0;j<4;j++)
                #pragma unroll
                for (int k=0;k<4;k++) acc[i][j][k]=0.f;

        for (int c = 0; c < 8; c++){
            if (c == 7) CP_WAIT0(); else CP_WAIT1();
            __syncthreads();
            uint32_t sW = sb + ZR_W_OFF + (c & 1)*ZR_WSTG;
            #pragma unroll
            for (int s = 0; s < 2; s++){
                int kg = c*2 + s;
                uint32_t a[2][4];
                #pragma unroll
                for (int i = 0; i < 2; i++){
                    int rl = wm*32 + i*16 + (lane & 7) + ((lane & 8) ? 8 : 0);
                    uint32_t colb = kg*32 + ((lane & 16) ? 16 : 0);
                    ldsm4(a[i], sb + ZR_A_OFF + rl*ZR_ROWSTR + colb);
                }
                uint32_t bf[4][2];
                #pragma unroll
                for (int jp = 0; jp < 2; jp++){
                    int nl = wn*32 + jp*16 + (lane & 7) + ((lane & 16) ? 8 : 0);
                    uint32_t colb = s*32 + ((lane & 8) ? 16 : 0);
                    uint32_t t4[4];
                    ldsm4(t4, sW + nl*80 + colb);
                    bf[2*jp][0]=t4[0]; bf[2*jp][1]=t4[1]; bf[2*jp+1][0]=t4[2]; bf[2*jp+1][1]=t4[3];
                }
                #pragma unroll
                for (int i=0;i<2;i++)
                    #pragma unroll
                    for (int j=0;j<4;j++) mma_f16(acc[i][j], a[i], bf[j]);
            }
            __syncthreads();
            if (c + 2 < 8) wload(Wg, c + 2, c & 1);
        }
        if (pass < 3){
            const h16* Wn = Wzrm + (size_t)(pass+1)*(128*256);
            wload(Wn, 0, 0);
            wload(Wn, 1, 1);
        }

        #pragma unroll
        for (int j = 0; j < 4; j++){
            int ccl = wn*32 + j*8 + (lane & 3)*2;
            #pragma unroll
            for (int i = 0; i < 2; i++){
                #pragma unroll
                for (int h = 0; h < 2; h++){
                    int rl = wm*32 + i*16 + (lane >> 2) + h*8;
                    int rr = m0 + rl;
                    *reinterpret_cast<__half2*>(zrraw + (size_t)rr*512 + pass*128 + ccl) =
                        __floats2half2_rn(acc[i][j][2*h], acc[i][j][2*h+1]);
                }
            }
        }
    }
}

// ================== k_gru_h: rm build + h GEMM + combine ==================
#define GH_ROWSTR 528
#define GH_A_OFF  0
#define GH_RM_OFF 33792
#define GH_W_OFF  67584
#define GH_WSTG   10240
#define GH_SMEM   88064

__global__ void __launch_bounds__(256,2) k_gru_h(
    const float* __restrict__ memory,
    const h16* __restrict__ Whm,
    const h16* __restrict__ zrraw,
    const h16* __restrict__ ozh,
    float* __restrict__ out_mem)
{
    extern __shared__ char smem[];
    uint32_t sb = smem_u32(smem);
    const int tid = threadIdx.x, lane = tid & 31, w = tid >> 5;
    const int wm = w >> 2, wn = w & 3;
    const int m0 = blockIdx.x * 64;

    auto wload = [&](const h16* Wg, int c, int s){
        #pragma unroll
        for (int t = 0; t < 2; t++){
            int u = tid + t*256;
            int row = u >> 2, q = u & 3;
            cpa16(sb + GH_W_OFF + s*GH_WSTG + row*80 + q*16,
                  Wg + (size_t)row*256 + c*32 + q*8);
        }
        CP_COMMIT();
    };
    wload(Whm, 0, 0);
    wload(Whm, 1, 1);

    // A: 64 rows fp32 -> fp16 SMEM
    #pragma unroll
    for (int t = 0; t < 8; t++){
        int u = tid + t*256;
        int row = u >> 5, q = u & 31;
        int rr = m0 + row, b = rr/9, m = rr - b*9 + 1;
        const float* src = memory + ((size_t)b*10 + m)*256 + q*8;
        float4 a = *reinterpret_cast<const float4*>(src);
        float4 c = *reinterpret_cast<const float4*>(src + 4);
        __half2 o0 = __floats2half2_rn(a.x, a.y);
        __half2 o1 = __floats2half2_rn(a.z, a.w);
        __half2 o2 = __floats2half2_rn(c.x, c.y);
        __half2 o3 = __floats2half2_rn(c.z, c.w);
        uint4 pk;
        pk.x = *reinterpret_cast<uint32_t*>(&o0);
        pk.y = *reinterpret_cast<uint32_t*>(&o1);
        pk.z = *reinterpret_cast<uint32_t*>(&o2);
        pk.w = *reinterpret_cast<uint32_t*>(&o3);
        *reinterpret_cast<uint4*>(smem + GH_A_OFF + row*GH_ROWSTR + q*16) = pk;
    }
    __syncthreads();

    // rm = sigmoid(rraw + ozh_r) * mem  -> RM SMEM (fp16)
    #pragma unroll
    for (int t = 0; t < 32; t++){
        int u = tid + t*256;              // over 64*128 half2
        int row = u >> 7, c2 = u & 127;
        int rr = m0 + row, b = rr/9;
        float2 rf = __half22float2(*reinterpret_cast<const __half2*>(zrraw + (size_t)rr*512 + 256 + c2*2));
        float2 oz = __half22float2(*reinterpret_cast<const __half2*>(ozh + (size_t)b*768 + 256 + c2*2));
        float2 mv = __half22float2(*reinterpret_cast<const __half2*>(smem + GH_A_OFF + row*GH_ROWSTR + c2*4));
        *reinterpret_cast<__half2*>(smem + GH_RM_OFF + row*GH_ROWSTR + c2*4) =
            __floats2half2_rn(sigf(rf.x+oz.x)*mv.x, sigf(rf.y+oz.y)*mv.y);
    }
    __syncthreads();

    for (int pass = 0; pass < 2; pass++){
        const h16* Wg = Whm + (size_t)pass*(128*256);
        float acc[2][4][4];
        #pragma unroll
        for (int i=0;i<2;i++)
            #pragma unroll
            for (int j=0;j<4;j++)
                #pragma unroll
                for (int k=0;k<4;k++) acc[i][j][k]=0.f;

        for (int c = 0; c < 8; c++){
            if (c == 7) CP_WAIT0(); else CP_WAIT1();
            __syncthreads();
            uint32_t sW = sb + GH_W_OFF + (c & 1)*GH_WSTG;
            #pragma unroll
            for (int s = 0; s < 2; s++){
                int kg = c*2 + s;
                uint32_t a[2][4];
                #pragma unroll
                for (int i = 0; i < 2; i++){
                    int rl = wm*32 + i*16 + (lane & 7) + ((lane & 8) ? 8 : 0);
                    uint32_t colb = kg*32 + ((lane & 16) ? 16 : 0);
                    ldsm4(a[i], sb + GH_RM_OFF + rl*GH_ROWSTR + colb);
                }
                uint32_t bf[4][2];
                #pragma unroll
                for (int jp = 0; jp < 2; jp++){
                    int nl = wn*32 + jp*16 + (lane & 7) + ((lane & 16) ? 8 : 0);
                    uint32_t colb = s*32 + ((lane & 8) ? 16 : 0);
                    uint32_t t4[4];
                    ldsm4(t4, sW + nl*80 + colb);
                    bf[2*jp][0]=t4[0]; bf[2*jp][1]=t4[1]; bf[2*jp+1][0]=t4[2]; bf[2*jp+1][1]=t4[3];
                }
                #pragma unroll
                for (int i=0;i<2;i++)
                    #pragma unroll
                    for (int j=0;j<4;j++) mma_f16(acc[i][j], a[i], bf[j]);
            }
            __syncthreads();
            if (c + 2 < 8) wload(Wg, c + 2, c & 1);
        }
        if (pass < 1){
            const h16* Wn = Whm + 128*256;
            wload(Wn, 0, 0);
            wload(Wn, 1, 1);
        }

        #pragma unroll
        for (int j = 0; j < 4; j++){
            int ccl = wn*32 + j*8 + (lane & 3)*2;
            int cc  = pass*128 + ccl;
            #pragma unroll
            for (int i = 0; i < 2; i++){
                #pragma unroll
                for (int h = 0; h < 2; h++){
                    int rl = wm*32 + i*16 + (lane >> 2) + h*8;
                    int rr = m0 + rl, b = rr/9, m = rr - b*9 + 1;
                    float v0 = acc[i][j][2*h], v1 = acc[i][j][2*h+1];
                    float2 ozh_h = __half22float2(*reinterpret_cast<const __half2*>(ozh + (size_t)b*768 + 512 + cc));
                    float mt0 = tanhf(v0 + ozh_h.x), mt1 = tanhf(v1 + ozh_h.y);
                    float2 zr = __half22float2(*reinterpret_cast<const __half2*>(zrraw + (size_t)rr*512 + cc));
                    float2 ozz = __half22float2(*reinterpret_cast<const __half2*>(ozh + (size_t)b*768 + cc));
                    float z0 = sigf(zr.x + ozz.x), z1 = sigf(zr.y + ozz.y);
                    float2 mv = __half22float2(*reinterpret_cast<const __half2*>(smem + GH_A_OFF + rl*GH_ROWSTR + cc*2));
                    *reinterpret_cast<float2*>(out_mem + (size_t)b*(ML_*256) + (size_t)(m-1)*256 + cc) =
                        make_float2(z0*mv.x + (1.f-z0)*mt0, z1*mv.y + (1.f-z1)*mt1);
                }
            }
        }
    }
}

// ---------------- fused front launch: weights + Wqk + biases + frame ----------------
#define PB_QK    256
#define PB_BIAS  6
#define PB_WIGO  1536
#define PB_WZRM  512
#define PB_WHM   256
#define PB_WOZH  768
#define PB_WV    256
#define PB_FRAME 16384
#define PB_TOTAL (PB_QK+PB_BIAS+PB_WIGO+PB_WZRM+PB_WHM+PB_WOZH+PB_WV+PB_FRAME)

__global__ void k_prep_all(const float* __restrict__ qW, const float* __restrict__ kW,
                           const float* __restrict__ qb,
                           const float* __restrict__ Wih,
                           const float* __restrict__ bih, const float* __restrict__ bhh,
                           const float* __restrict__ vW,
                           const float* __restrict__ zW, const float* __restrict__ rW,
                           const float* __restrict__ hW,
                           const float* __restrict__ zb, const float* __restrict__ rb,
                           const float* __restrict__ hb,
                           const float* __restrict__ O_t, const float* __restrict__ O_prev,
                           const float* __restrict__ wW, const float* __restrict__ wb,
                           float* __restrict__ out_Wt)
{
    int blk = blockIdx.x;
    if (blk < PB_QK){
        int j = blk, e = threadIdx.x;
        float s = 0.f;
        for (int d = 0; d < 256; d++) s = fmaf(qW[d*256 + e], kW[d*256 + j], s);
        g_Wqk[j*256 + e] = __float2half_rn(s);
        if (e == 0){
            float bq = 0.f;
            for (int d = 0; d < 256; d++) bq = fmaf(qb[d], kW[d*256 + j], bq);
            g_bqk[j] = bq;
        }
        return;
    } blk -= PB_QK;
    if (blk < PB_BIAS){
        int i = blk*256 + threadIdx.x;
        if (i < 768){
            int src = (i < 256) ? i : i + 256;
            g_bigo[i] = bih[src] + bhh[src];
        } else if (i < 1536){
            int n = i - 768;
            g_bozh[n] = (n < 256) ? zb[n] : (n < 512) ? rb[n-256] : hb[n-512];
        }
        return;
    } blk -= PB_BIAS;
    if (blk < PB_WIGO){
        int i = blk*256 + threadIdx.x;
        int n = i >> 9, k = i & 511;
        int src = (n < 256) ? n : n + 256;
        g_Wigo[i] = __float2half_rn(Wih[(size_t)src*512 + k]);
        return;
    } blk -= PB_WIGO;
    if (blk < PB_WZRM){
        int i = blk*256 + threadIdx.x;
        int n = i >> 8, k = i & 255;
        float v = (n < 256) ? zW[(size_t)n*512 + k] : rW[(size_t)(n-256)*512 + k];
        g_Wzrm[i] = __float2half_rn(v);
        return;
    } blk -= PB_WZRM;
    if (blk < PB_WHM){
        int i = blk*256 + threadIdx.x;
        int n = i >> 8, k = i & 255;
        g_Whm[i] = __float2half_rn(hW[(size_t)n*512 + k]);
        return;
    } blk -= PB_WHM;
    if (blk < PB_WOZH){
        int i = blk*256 + threadIdx.x;
        int n = i >> 8, k = i & 255;
        float v = (n < 256) ? zW[(size_t)n*512 + 256 + k]
                : (n < 512) ? rW[(size_t)(n-256)*512 + 256 + k]
                            : hW[(size_t)(n-512)*512 + 256 + k];
        g_Wozh[i] = __float2half_rn(v);
        return;
    } blk -= PB_WOZH;
    if (blk < PB_WV){
        int i = blk*256 + threadIdx.x;
        g_Wv[i] = __float2half_rn(vW[i]);
        return;
    } blk -= PB_WV;
    {
        int b = blk, t = threadIdx.x;
        float ot = O_t[(size_t)b*256 + t];
        float op = O_prev[(size_t)b*256 + t];
        float dl = ot - op;
        float s0 = ot*ot, s1 = op*op, s2 = dl*dl, s3 = ot*op;
        #pragma unroll
        for (int off = 16; off; off >>= 1){
            s0 += __shfl_xor_sync(0xffffffffu, s0, off);
            s1 += __shfl_xor_sync(0xffffffffu, s1, off);
            s2 += __shfl_xor_sync(0xffffffffu, s2, off);
            s3 += __shfl_xor_sync(0xffffffffu, s3, off);
        }
        __shared__ float4 ws[8];
        __shared__ float4 tot;
        int w = t >> 5;
        if ((t & 31) == 0) ws[w] = make_float4(s0, s1, s2, s3);
        __syncthreads();
        if (t == 0){
            float4 r = ws[0];
            #pragma unroll
            for (int i = 1; i < 8; i++){ r.x += ws[i].x; r.y += ws[i].y; r.z += ws[i].z; r.w += ws[i].w; }
            tot = r;
        }
        __syncthreads();
        float n_t = sqrtf(tot.x), n_p = sqrtf(tot.y), rd = sqrtf(tot.z);
        float ra  = tot.w / (n_t*n_p + 1e-6f);
        float wt  = 0.5f*(tanhf(n_t*wW[t*3+0] + rd*wW[t*3+1] + ra*wW[t*3+2] + wb[t]) + 1.f);
        out_Wt[(size_t)b*256 + t] = wt;
        g_X[(size_t)b*512 + t]       = __float2half_rn(op);
        g_X[(size_t)b*512 + 256 + t] = __float2half_rn(ot * wt);
    }
}

// ---------------- LSTM activations (half2-vectorized) ----------------
__global__ void k_lstm_act(){
    int i = blockIdx.x*256 + threadIdx.x;
    const __half2* G = reinterpret_cast<const __half2*>(g_gates);
    int b = i >> 7, d2 = i & 127;
    float2 ig = __half22float2(G[(size_t)b*384 + d2]);
    float2 gg = __half22float2(G[(size_t)b*384 + 128 + d2]);
    float2 og = __half22float2(G[(size_t)b*384 + 256 + d2]);
    float c0 = sigf(ig.x) * tanhf(gg.x);
    float c1 = sigf(ig.y) * tanhf(gg.y);
    reinterpret_cast<__half2*>(g_OTP)[i] =
        __floats2half2_rn(sigf(og.x)*tanhf(c0), sigf(og.y)*tanhf(c1));
}

// ---------------- attention v3: 1 warp per batch row, fp32 memory source ----------------
__global__ void __launch_bounds__(256) k_attn(const float* __restrict__ memory){
    int b = blockIdx.x*8 + (threadIdx.x >> 5);
    int lane = threadIdx.x & 31;

    uint4 qv = *reinterpret_cast<const uint4*>(g_QK + (size_t)b*256 + lane*8);
    float qf[8];
    {
        float2 t;
        t = __half22float2(*reinterpret_cast<__half2*>(&qv.x)); qf[0]=t.x; qf[1]=t.y;
        t = __half22float2(*reinterpret_cast<__half2*>(&qv.y)); qf[2]=t.x; qf[3]=t.y;
        t = __half22float2(*reinterpret_cast<__half2*>(&qv.z)); qf[4]=t.x; qf[5]=t.y;
        t = __half22float2(*reinterpret_cast<__half2*>(&qv.w)); qf[6]=t.x; qf[7]=t.y;
    }

    float mv[ML_][8];
    float sc[ML_];
    const float* mb = memory + (size_t)b*ML_*256;
    #pragma unroll
    for (int m = 0; m < ML_; m++){
        float4 a = *reinterpret_cast<const float4*>(mb + m*256 + lane*8);
        float4 c = *reinterpret_cast<const float4*>(mb + m*256 + lane*8 + 4);
        mv[m][0]=a.x; mv[m][1]=a.y; mv[m][2]=a.z; mv[m][3]=a.w;
        mv[m][4]=c.x; mv[m][5]=c.y; mv[m][6]=c.z; mv[m][7]=c.w;
        float s = 0.f;
        #pragma unroll
        for (int q = 0; q < 8; q++) s = fmaf(qf[q], mv[m][q], s);
        #pragma unroll
        for (int off = 16; off; off >>= 1) s += __shfl_xor_sync(0xffffffffu, s, off);
        sc[m] = s * 0.0625f;
    }
    float mx = sc[0];
    #pragma unroll
    for (int m = 1; m < ML_; m++) mx = fmaxf(mx, sc[m]);
    float e[ML_], ssum = 0.f;
    #pragma unroll
    for (int m = 0; m < ML_; m++){ e[m] = expf(sc[m] - mx); ssum += e[m]; }
    float inv = 1.f / ssum;

    float wm[8];
    #pragma unroll
    for (int q = 0; q < 8; q++) wm[q] = 0.f;
    #pragma unroll
    for (int m = 0; m < ML_; m++){
        float am = e[m] * inv;
        #pragma unroll
        for (int q = 0; q < 8; q++) wm[q] = fmaf(am, mv[m][q], wm[q]);
    }
    __half2 o0 = __floats2half2_rn(wm[0], wm[1]);
    __half2 o1 = __floats2half2_rn(wm[2], wm[3]);
    __half2 o2 = __floats2half2_rn(wm[4], wm[5]);
    __half2 o3 = __floats2half2_rn(wm[6], wm[7]);
    uint4 pk;
    pk.x = *reinterpret_cast<uint32_t*>(&o0);
    pk.y = *reinterpret_cast<uint32_t*>(&o1);
    pk.z = *reinterpret_cast<uint32_t*>(&o2);
    pk.w = *reinterpret_cast<uint32_t*>(&o3);
    *reinterpret_cast<uint4*>(g_WM + (size_t)b*256 + lane*8) = pk;
}

// ---------------- launcher ----------------
extern "C" void kernel_launch(void* const* d_in, const int* in_sizes, int n_in,
                              void* d_out, int out_size)
{
    const float* O_t     = (const float*)d_in[0];
    const float* O_prev  = (const float*)d_in[1];
    const float* memory  = (const float*)d_in[2];
    const float* w_mlp_W = (const float*)d_in[3];
    const float* w_mlp_b = (const float*)d_in[4];
    const float* lstm_Wih= (const float*)d_in[5];
    const float* lstm_bih= (const float*)d_in[7];
    const float* lstm_bhh= (const float*)d_in[8];
    const float* q_W = (const float*)d_in[9];   const float* q_b = (const float*)d_in[10];
    const float* k_W = (const float*)d_in[11];  // k_b cancels in softmax
    const float* v_W = (const float*)d_in[13];  const float* v_b = (const float*)d_in[14];
    const float* z_W = (const float*)d_in[15];  const float* z_b = (const float*)d_in[16];
    const float* r_W = (const float*)d_in[17];  const float* r_b = (const float*)d_in[18];
    const float* h_W = (const float*)d_in[19];  const float* h_b = (const float*)d_in[20];

    float* out      = (float*)d_out;
    float* out0     = out;
    float* out_mem  = out0 + (size_t)B_*D_;
    float* out2     = out_mem + (size_t)B_*ML_*D_;
    float* out3     = out2 + (size_t)B_*D_;

    static cudaStream_t s1 = nullptr;
    static cudaEvent_t evFork = nullptr, evJoin = nullptr;
    if (s1 == nullptr){
        cudaStreamCreateWithFlags(&s1, cudaStreamNonBlocking);
        cudaEventCreateWithFlags(&evFork, cudaEventDisableTiming);
        cudaEventCreateWithFlags(&evJoin, cudaEventDisableTiming);
        cudaFuncSetAttribute(k_mma<5>, cudaFuncAttributeMaxDynamicSharedMemorySize, SMEM_TOTAL);
        cudaFuncSetAttribute(k_mma<2>, cudaFuncAttributeMaxDynamicSharedMemorySize, SMEM_TOTAL);
        cudaFuncSetAttribute(k_zr,     cudaFuncAttributeMaxDynamicSharedMemorySize, ZR_SMEM);
        cudaFuncSetAttribute(k_gru_h,  cudaFuncAttributeMaxDynamicSharedMemorySize, GH_SMEM);
    }

    float *pbigo,*pbozh,*pbqk;
    h16 *pQK,*pGates,*pOZH,*pX,*pOTP,*pWM,*pOUP,*pZRraw;
    h16 *pWigo,*pWqk,*pWv,*pWzrm,*pWhm,*pWozh;
    cudaGetSymbolAddress((void**)&pQK,    g_QK);
    cudaGetSymbolAddress((void**)&pbigo,  g_bigo);
    cudaGetSymbolAddress((void**)&pbozh,  g_bozh);
    cudaGetSymbolAddress((void**)&pbqk,   g_bqk);
    cudaGetSymbolAddress((void**)&pGates, g_gates);
    cudaGetSymbolAddress((void**)&pOZH,   g_OZH);
    cudaGetSymbolAddress((void**)&pX,     g_X);
    cudaGetSymbolAddress((void**)&pOTP,   g_OTP);
    cudaGetSymbolAddress((void**)&pWM,    g_WM);
    cudaGetSymbolAddress((void**)&pOUP,   g_OUP);
    cudaGetSymbolAddress((void**)&pZRraw, g_ZRraw);
    cudaGetSymbolAddress((void**)&pWigo,  g_Wigo);
    cudaGetSymbolAddress((void**)&pWqk,   g_Wqk);
    cudaGetSymbolAddress((void**)&pWv,    g_Wv);
    cudaGetSymbolAddress((void**)&pWzrm,  g_Wzrm);
    cudaGetSymbolAddress((void**)&pWhm,   g_Whm);
    cudaGetSymbolAddress((void**)&pWozh,  g_Wozh);

    // 1: fused front (weights + Wqk + biases + frame)
    k_prep_all<<<PB_TOTAL, 256>>>(q_W, k_W, q_b, lstm_Wih, lstm_bih, lstm_bhh,
                                  v_W, z_W, r_W, h_W, z_b, r_b, h_b,
                                  O_t, O_prev, w_mlp_W, w_mlp_b, out3);

    // fork: raw z|r GEMM on side stream (needs only memory + Wzrm)
    cudaEventRecord(evFork, 0);
    cudaStreamWaitEvent(s1, evFork, 0);
    k_zr<<<M2_/64, 256, ZR_SMEM, s1>>>(memory, pWzrm, pZRraw);
    cudaEventRecord(evJoin, s1);

    // 2: LSTM gates [B,768] fp16, K=512
    k_mma<5><<<dim3(6, B_/128), 256, SMEM_TOTAL>>>(
        pX, pWigo, pbigo, pGates, nullptr, nullptr, nullptr,
        B_, 768, 512);
    // 3: LSTM activations -> OTP (fp16)
    k_lstm_act<<<(B_*128)/256, 256>>>();
    // 4: QK = OTP @ Wqk^T + bqk  [B,256] fp16
    k_mma<5><<<dim3(2, B_/128), 256, SMEM_TOTAL>>>(
        pOTP, pWqk, pbqk, pQK, nullptr, nullptr, nullptr,
        B_, 256, 256);
    // 5: attention v3 (fp32 memory source) -> WM (fp16)
    k_attn<<<B_/8, 256>>>(memory);
    // 6: V GEMM -> OUP (fp16) + out0/out2/mem slot 9 (fp32)
    k_mma<2><<<dim3(2, B_/128), 256, SMEM_TOTAL>>>(
        pWM, pWv, v_b, pOUP, out0, out_mem, out2,
        B_, 256, 256);
    // 7: OZH = O_up @ Wozh^T + bozh  [B,768] fp16
    k_mma<5><<<dim3(6, B_/128), 256, SMEM_TOTAL>>>(
        pOUP, pWozh, pbozh, pOZH, nullptr, nullptr, nullptr,
        B_, 768, 256);

    // join, then final GRU-h (rm build + h GEMM + combine)
    cudaStreamWaitEvent(0, evJoin, 0);
    k_gru_h<<<M2_/64, 256, GH_SMEM>>>(memory, pWhm, pZRraw, pOZH, out_mem);
}